// round 16
// baseline (speedup 1.0000x reference)
#include <cuda_runtime.h>
#include <math.h>

// ---------------------------------------------------------------------------
// Problem constants
// ---------------------------------------------------------------------------
#define Bc   4
#define Lc   2048
#define DINc 80
#define Dc   128
#define Hc   16
#define DHc  8
#define DFFc 128
#define WINc 64
#define Mrows (Bc * Lc)        // 8192

typedef unsigned long long ull;

// ---------------------------------------------------------------------------
// Scratch (device globals: allocation-free)
// ---------------------------------------------------------------------------
__device__ float g_h  [Mrows * Dc];
__device__ float g_q  [Bc * Hc * Lc * DHc];   // [B,H,L,8]
__device__ float g_kb [Bc * Hc * Lc * DHc];
__device__ float g_vb [Bc * Hc * Lc * DHc];
__device__ float g_ctx[Mrows * Dc];
__device__ float g_ao [Mrows * Dc];
__device__ float g_f  [Mrows * DFFc];
__device__ float g_g2 [Mrows * Dc];
__device__ float g_pe [Lc * Dc];

// ---------------------------------------------------------------------------
// f32x2 packed-FMA helpers (PTX-only; doubles fp32 FMA throughput on sm_103a)
// ---------------------------------------------------------------------------
__device__ __forceinline__ ull pack2(float x, float y) {
    ull r; asm("mov.b64 %0, {%1, %2};" : "=l"(r) : "f"(x), "f"(y)); return r;
}
__device__ __forceinline__ void unpack2(ull v, float& x, float& y) {
    asm("mov.b64 {%0, %1}, %2;" : "=f"(x), "=f"(y) : "l"(v));
}
__device__ __forceinline__ void fma2(ull& d, ull a, ull b) {
    asm("fma.rn.f32x2 %0, %1, %2, %0;" : "+l"(d) : "l"(a), "l"(b));
}

// ---------------------------------------------------------------------------
// Positional encoding: pair j=d>>1, even->sin, odd->cos, 10000^(j/128)
// ---------------------------------------------------------------------------
__global__ void pe_kernel(float* __restrict__ pe) {
    int l = blockIdx.x;
    int d = threadIdx.x;
    int j = d >> 1;
    float pj  = powf(10000.0f, (float)j / 128.0f);
    float ang = (float)l / pj;
    pe[l * Dc + d] = (d & 1) ? cosf(ang) : sinf(ang);
}

// ---------------------------------------------------------------------------
// Tiled SGEMM: C[M,N] = A[M,K] @ W[N,K]^T (+bias, +epilogue)
// BM=32, BN=128, K resident (compile-time), 256 threads.
// Micro-tile: 2 rows x 8 cols. A row-major in smem (broadcast reads);
// W transposed [k][n] (ulonglong2 pair reads). One sync pair total.
// Grid: (ceil(N/128), M/32) -> 256+ blocks, 2 blocks/SM.
// MODE: 0 bias | 1 bias+relu | 2 relu->BN->+pe | 3 qkv scatter [B,H,L,8]
// ---------------------------------------------------------------------------
template <int MODE, int K>
__global__ void __launch_bounds__(256)
gemm_k(const float* __restrict__ A, const float* __restrict__ W,
       const float* __restrict__ bias, float* __restrict__ C,
       int N,
       const float* __restrict__ e0, const float* __restrict__ e1,
       const float* __restrict__ e2, const float* __restrict__ e3,
       const float* __restrict__ e4,
       float* __restrict__ o1, float* __restrict__ o2)
{
    constexpr int AK = K + 4;               // padded row stride
    extern __shared__ float smem[];
    float* As = smem;                       // [32][AK] row-major
    float* Ws = smem + 32 * AK;             // [K][128] transposed

    const int tid  = threadIdx.x;
    const int tx   = tid & 15;              // col group: 8 cols
    const int ty   = tid >> 4;              // row group: 2 rows
    const int row0 = blockIdx.y * 32;
    const int col0 = blockIdx.x * 128;

    // ---- fill A: row = tid&31, k-chunk = (tid>>5)*16 (4 float4)
    {
        const int mf = tid & 31;
        const int kq = tid >> 5;            // 0..7
        const float* Ap = A + (size_t)(row0 + mf) * K + kq * 16;
        #pragma unroll
        for (int u = 0; u < 4; u++) {
            const int kk = kq * 16 + u * 4;
            if (kk < K)
                *(float4*)&As[mf * AK + kk] = *(const float4*)(Ap + u * 4);
        }
    }
    // ---- fill W: col = tid&127, k-chunk = (tid>>7)*64 (16 float4)
    {
        const int nf = tid & 127;
        const int kh = tid >> 7;            // 0..1
        const bool wvalid = (col0 + nf) < N;
        const float* Wp = W + (size_t)(col0 + nf) * K + kh * 64;
        #pragma unroll
        for (int u = 0; u < 16; u++) {
            const int kk = kh * 64 + u * 4;
            if (kk < K) {
                float4 w4 = wvalid ? *(const float4*)(Wp + u * 4)
                                   : make_float4(0.f, 0.f, 0.f, 0.f);
                Ws[(kk + 0) * 128 + nf] = w4.x;
                Ws[(kk + 1) * 128 + nf] = w4.y;
                Ws[(kk + 2) * 128 + nf] = w4.z;
                Ws[(kk + 3) * 128 + nf] = w4.w;
            }
        }
    }
    __syncthreads();

    ull acc[2][4];
    #pragma unroll
    for (int i = 0; i < 2; i++)
        #pragma unroll
        for (int j = 0; j < 4; j++) acc[i][j] = 0ull;

    const float* a0p = &As[(ty * 2 + 0) * AK];
    const float* a1p = &As[(ty * 2 + 1) * AK];

    #pragma unroll 16
    for (int kk = 0; kk < K; kk++) {
        const float a0 = a0p[kk];
        const float a1 = a1p[kk];
        ulonglong2 wA = *(const ulonglong2*)&Ws[kk * 128 + tx * 8];
        ulonglong2 wB = *(const ulonglong2*)&Ws[kk * 128 + tx * 8 + 4];
        const ull d0 = pack2(a0, a0);
        const ull d1 = pack2(a1, a1);
        fma2(acc[0][0], d0, wA.x); fma2(acc[0][1], d0, wA.y);
        fma2(acc[0][2], d0, wB.x); fma2(acc[0][3], d0, wB.y);
        fma2(acc[1][0], d1, wA.x); fma2(acc[1][1], d1, wA.y);
        fma2(acc[1][2], d1, wB.x); fma2(acc[1][3], d1, wB.y);
    }

    // ---- epilogue: cols [colb, colb+8) fully in or fully out (N % 8 == 0)
    const int colb = col0 + tx * 8;
    if (colb + 7 >= N) return;

    float4 b0 = *(const float4*)(bias + colb);
    float4 b1 = *(const float4*)(bias + colb + 4);

    float4 gg0, gg1, be0, be1, rm0, rm1, rv0, rv1;
    if (MODE == 2) {
        gg0 = *(const float4*)(e0 + colb); gg1 = *(const float4*)(e0 + colb + 4);
        be0 = *(const float4*)(e1 + colb); be1 = *(const float4*)(e1 + colb + 4);
        rm0 = *(const float4*)(e2 + colb); rm1 = *(const float4*)(e2 + colb + 4);
        rv0 = *(const float4*)(e3 + colb); rv1 = *(const float4*)(e3 + colb + 4);
        gg0.x *= rsqrtf(rv0.x + 1e-5f); gg0.y *= rsqrtf(rv0.y + 1e-5f);
        gg0.z *= rsqrtf(rv0.z + 1e-5f); gg0.w *= rsqrtf(rv0.w + 1e-5f);
        gg1.x *= rsqrtf(rv1.x + 1e-5f); gg1.y *= rsqrtf(rv1.y + 1e-5f);
        gg1.z *= rsqrtf(rv1.z + 1e-5f); gg1.w *= rsqrtf(rv1.w + 1e-5f);
    }

    #pragma unroll
    for (int i = 0; i < 2; i++) {
        const int m = row0 + ty * 2 + i;
        float v[8];
        unpack2(acc[i][0], v[0], v[1]);
        unpack2(acc[i][1], v[2], v[3]);
        unpack2(acc[i][2], v[4], v[5]);
        unpack2(acc[i][3], v[6], v[7]);
        v[0] += b0.x; v[1] += b0.y; v[2] += b0.z; v[3] += b0.w;
        v[4] += b1.x; v[5] += b1.y; v[6] += b1.z; v[7] += b1.w;

        if (MODE == 0 || MODE == 1) {
            if (MODE == 1)
                #pragma unroll
                for (int j = 0; j < 8; j++) v[j] = fmaxf(v[j], 0.0f);
            float* cp = C + (size_t)m * N + colb;
            *(float4*)cp       = make_float4(v[0], v[1], v[2], v[3]);
            *(float4*)(cp + 4) = make_float4(v[4], v[5], v[6], v[7]);
        } else if (MODE == 2) {
            const int l = m & (Lc - 1);
            float4 p0 = *(const float4*)(e4 + (size_t)l * Dc + colb);
            float4 p1 = *(const float4*)(e4 + (size_t)l * Dc + colb + 4);
            #pragma unroll
            for (int j = 0; j < 8; j++) v[j] = fmaxf(v[j], 0.0f);
            v[0] = (v[0] - rm0.x) * gg0.x + be0.x + p0.x;
            v[1] = (v[1] - rm0.y) * gg0.y + be0.y + p0.y;
            v[2] = (v[2] - rm0.z) * gg0.z + be0.z + p0.z;
            v[3] = (v[3] - rm0.w) * gg0.w + be0.w + p0.w;
            v[4] = (v[4] - rm1.x) * gg1.x + be1.x + p1.x;
            v[5] = (v[5] - rm1.y) * gg1.y + be1.y + p1.y;
            v[6] = (v[6] - rm1.z) * gg1.z + be1.z + p1.z;
            v[7] = (v[7] - rm1.w) * gg1.w + be1.w + p1.w;
            float* cp = C + (size_t)m * Dc + colb;
            *(float4*)cp       = make_float4(v[0], v[1], v[2], v[3]);
            *(float4*)(cp + 4) = make_float4(v[4], v[5], v[6], v[7]);
        } else {  // MODE 3: qkv scatter -> [B,H,L,8]
            const int which = col0 >> 7;      // block x = 0:q 1:k 2:v
            const int hh = tx;
            const int b  = m >> 11;
            const int l  = m & (Lc - 1);
            float* dst = (which == 0) ? C : ((which == 1) ? o1 : o2);
            float* dp = dst + (((size_t)(b * Hc + hh)) * Lc + l) * DHc;
            *(float4*)dp       = make_float4(v[0], v[1], v[2], v[3]);
            *(float4*)(dp + 4) = make_float4(v[4], v[5], v[6], v[7]);
        }
    }
}

// ---------------------------------------------------------------------------
// Local-window attention: 4 queries per thread, d-pair float2 smem, f32x2.
// Block: 128 threads -> 512 consecutive queries of one (b,h).
// Each thread owns queries qb..qb+3; loops jj over 132 candidate keys,
// loading each K/V row ONCE and scoring all 4 queries against it
// (8x less smem traffic than 1-query-per-thread).
// Window per query: 1 <= |j-q| <= 64 (diagonal excluded), 0 <= j < L.
// Softmax without max-subtraction (scores are small; exact ratio in fp32).
// ---------------------------------------------------------------------------
#define ATHR  128
#define AQPT  4
#define AQB   (ATHR * AQPT)       // 512 queries per block
#define AROWS (AQB + 2 * WINc)    // 640 staged rows

__global__ void __launch_bounds__(ATHR)
attn_kernel(const float* __restrict__ Q, const float* __restrict__ Kb,
            const float* __restrict__ Vb, float* __restrict__ ctx)
{
    __shared__ float2 Kp[4][AROWS];
    __shared__ float2 Vp[4][AROWS];

    const int tid = threadIdx.x;
    const int q0  = blockIdx.x * AQB;
    const int bh  = blockIdx.y;               // b*H + h

    const float* kp = Kb + (size_t)bh * Lc * DHc;
    const float* vp = Vb + (size_t)bh * Lc * DHc;

    #pragma unroll
    for (int rr = 0; rr < AROWS / ATHR; rr++) {
        const int r = tid + rr * ATHR;
        const int g = q0 - WINc + r;
        if (g >= 0 && g < Lc) {
            float4 k0 = *(const float4*)(kp + (size_t)g * DHc);
            float4 k1 = *(const float4*)(kp + (size_t)g * DHc + 4);
            Kp[0][r] = make_float2(k0.x, k0.y);
            Kp[1][r] = make_float2(k0.z, k0.w);
            Kp[2][r] = make_float2(k1.x, k1.y);
            Kp[3][r] = make_float2(k1.z, k1.w);
            float4 v0 = *(const float4*)(vp + (size_t)g * DHc);
            float4 v1 = *(const float4*)(vp + (size_t)g * DHc + 4);
            Vp[0][r] = make_float2(v0.x, v0.y);
            Vp[1][r] = make_float2(v0.z, v0.w);
            Vp[2][r] = make_float2(v1.x, v1.y);
            Vp[3][r] = make_float2(v1.z, v1.w);
        } else {
            Kp[0][r] = Kp[1][r] = Kp[2][r] = Kp[3][r] = make_float2(0.f, 0.f);
            Vp[0][r] = Vp[1][r] = Vp[2][r] = Vp[3][r] = make_float2(0.f, 0.f);
        }
    }
    __syncthreads();

    const int qb = q0 + tid * AQPT;           // first of this thread's 4 queries

    ull qd[AQPT][4];
    #pragma unroll
    for (int i = 0; i < AQPT; i++) {
        const float* qp = Q + ((size_t)bh * Lc + qb + i) * DHc;
        float4 qa = *(const float4*)qp;
        float4 qv = *(const float4*)(qp + 4);
        qd[i][0] = pack2(qa.x, qa.y); qd[i][1] = pack2(qa.z, qa.w);
        qd[i][2] = pack2(qv.x, qv.y); qd[i][3] = pack2(qv.z, qv.w);
    }

    const float scale = 0.35355339059327373f; // 1/sqrt(8)
    float sum[AQPT] = {0.f, 0.f, 0.f, 0.f};
    ull c2[AQPT][4];
    #pragma unroll
    for (int i = 0; i < AQPT; i++)
        #pragma unroll
        for (int d = 0; d < 4; d++) c2[i][d] = 0ull;

    // jj scans keys j = qb - 64 + jj, jj in [0, 128 + AQPT)
    #pragma unroll 4
    for (int jj = 0; jj < 128 + AQPT; jj++) {
        const int r = tid * AQPT + jj;        // local staged row
        const int j = qb - WINc + jj;         // global key index
        const bool jok = ((unsigned)j < (unsigned)Lc);

        const ull k0 = *(const ull*)&Kp[0][r];
        const ull k1 = *(const ull*)&Kp[1][r];
        const ull k2 = *(const ull*)&Kp[2][r];
        const ull k3 = *(const ull*)&Kp[3][r];
        const ull v0 = *(const ull*)&Vp[0][r];
        const ull v1 = *(const ull*)&Vp[1][r];
        const ull v2 = *(const ull*)&Vp[2][r];
        const ull v3 = *(const ull*)&Vp[3][r];

        #pragma unroll
        for (int i = 0; i < AQPT; i++) {
            // offset of key from query i: d = j - (qb+i) = jj - 64 - i
            const int doff = jj - WINc - i;
            const bool ok = jok && (doff != 0) && (doff >= -WINc) && (doff <= WINc);
            ull s2 = 0ull;
            fma2(s2, qd[i][0], k0);
            fma2(s2, qd[i][1], k1);
            fma2(s2, qd[i][2], k2);
            fma2(s2, qd[i][3], k3);
            float slo, shi; unpack2(s2, slo, shi);
            float p = __expf((slo + shi) * scale);
            p = ok ? p : 0.0f;
            sum[i] += p;
            const ull p2 = pack2(p, p);
            fma2(c2[i][0], p2, v0);
            fma2(c2[i][1], p2, v1);
            fma2(c2[i][2], p2, v2);
            fma2(c2[i][3], p2, v3);
        }
    }

    const int hh = bh & (Hc - 1);
    const int b  = bh >> 4;
    #pragma unroll
    for (int i = 0; i < AQPT; i++) {
        const float inv = 1.0f / sum[i];
        float o[8];
        unpack2(c2[i][0], o[0], o[1]);
        unpack2(c2[i][1], o[2], o[3]);
        unpack2(c2[i][2], o[4], o[5]);
        unpack2(c2[i][3], o[6], o[7]);
        #pragma unroll
        for (int d = 0; d < 8; d++) o[d] *= inv;
        float* op = ctx + ((size_t)(b * Lc + qb + i)) * Dc + hh * DHc;
        *(float4*)op       = make_float4(o[0], o[1], o[2], o[3]);
        *(float4*)(op + 4) = make_float4(o[4], o[5], o[6], o[7]);
    }
}

// ---------------------------------------------------------------------------
// Launch
// ---------------------------------------------------------------------------
extern "C" void kernel_launch(void* const* d_in, const int* in_sizes, int n_in,
                              void* d_out, int out_size)
{
    const float* x         = (const float*)d_in[0];
    const float* conv_w    = (const float*)d_in[1];
    const float* conv_b    = (const float*)d_in[2];
    const float* bn_g      = (const float*)d_in[3];
    const float* bn_b      = (const float*)d_in[4];
    const float* bn_rm     = (const float*)d_in[5];
    const float* bn_rv     = (const float*)d_in[6];
    const float* in_proj_w = (const float*)d_in[7];
    const float* in_proj_b = (const float*)d_in[8];
    const float* out_w     = (const float*)d_in[9];
    const float* out_b     = (const float*)d_in[10];
    const float* ff_w1     = (const float*)d_in[11];
    const float* ff_b1     = (const float*)d_in[12];
    const float* ff_w2     = (const float*)d_in[13];
    const float* ff_b2     = (const float*)d_in[14];
    const float* fc_w      = (const float*)d_in[15];
    const float* fc_b      = (const float*)d_in[16];
    float* out = (float*)d_out;

    float *h, *q, *kb, *vb, *ctx, *ao, *f, *g2, *pe;
    cudaGetSymbolAddress((void**)&h,   g_h);
    cudaGetSymbolAddress((void**)&q,   g_q);
    cudaGetSymbolAddress((void**)&kb,  g_kb);
    cudaGetSymbolAddress((void**)&vb,  g_vb);
    cudaGetSymbolAddress((void**)&ctx, g_ctx);
    cudaGetSymbolAddress((void**)&ao,  g_ao);
    cudaGetSymbolAddress((void**)&f,   g_f);
    cudaGetSymbolAddress((void**)&g2,  g_g2);
    cudaGetSymbolAddress((void**)&pe,  g_pe);

    // dynamic smem sizes
    const int SM80  = (32 * (80  + 4) + 80  * 128) * 4;   // 51712
    const int SM128 = (32 * (128 + 4) + 128 * 128) * 4;   // 82432

    static bool attr_done = false;
    if (!attr_done) {
        cudaFuncSetAttribute(gemm_k<2, 80>,  cudaFuncAttributeMaxDynamicSharedMemorySize, SM80);
        cudaFuncSetAttribute(gemm_k<3, 128>, cudaFuncAttributeMaxDynamicSharedMemorySize, SM128);
        cudaFuncSetAttribute(gemm_k<0, 128>, cudaFuncAttributeMaxDynamicSharedMemorySize, SM128);
        cudaFuncSetAttribute(gemm_k<1, 128>, cudaFuncAttributeMaxDynamicSharedMemorySize, SM128);
        attr_done = true;
    }

    // 0) positional encoding
    pe_kernel<<<Lc, Dc>>>(pe);

    // 1) conv(k=1)+relu+BN+pe : K=80, N=128, grid (1,256)
    gemm_k<2, 80><<<dim3(1, Mrows / 32), 256, SM80>>>(x, conv_w, conv_b, h,
        Dc, bn_g, bn_b, bn_rm, bn_rv, pe, nullptr, nullptr);

    // 2) qkv projection -> scatter [B,H,L,8] : N=384, grid (3,256)
    gemm_k<3, 128><<<dim3(3, Mrows / 32), 256, SM128>>>(h, in_proj_w, in_proj_b, q,
        3 * Dc, nullptr, nullptr, nullptr, nullptr, nullptr, kb, vb);

    // 3) local-window attention -> ctx [B,L,128] : grid (4,64)
    attn_kernel<<<dim3(Lc / AQB, Bc * Hc), ATHR>>>(q, kb, vb, ctx);

    // 4) out projection
    gemm_k<0, 128><<<dim3(1, Mrows / 32), 256, SM128>>>(ctx, out_w, out_b, ao,
        Dc, nullptr, nullptr, nullptr, nullptr, nullptr, nullptr, nullptr);

    // 5) ffn layer 1 (relu)
    gemm_k<1, 128><<<dim3(1, Mrows / 32), 256, SM128>>>(ao, ff_w1, ff_b1, f,
        DFFc, nullptr, nullptr, nullptr, nullptr, nullptr, nullptr, nullptr);

    // 6) ffn layer 2
    gemm_k<0, 128><<<dim3(1, Mrows / 32), 256, SM128>>>(f, ff_w2, ff_b2, g2,
        Dc, nullptr, nullptr, nullptr, nullptr, nullptr, nullptr, nullptr);

    // 7) final head -> [8192,80]
    gemm_k<0, 128><<<dim3(1, Mrows / 32), 256, SM128>>>(g2, fc_w, fc_b, out,
        DINc, nullptr, nullptr, nullptr, nullptr, nullptr, nullptr, nullptr);
}

// round 17
// speedup vs baseline: 1.7425x; 1.7425x over previous
#include <cuda_runtime.h>
#include <math.h>

// ---------------------------------------------------------------------------
// Problem constants
// ---------------------------------------------------------------------------
#define Bc   4
#define Lc   2048
#define DINc 80
#define Dc   128
#define Hc   16
#define DHc  8
#define DFFc 128
#define WINc 64
#define Mrows (Bc * Lc)        // 8192

typedef unsigned long long ull;

// ---------------------------------------------------------------------------
// Scratch (device globals: allocation-free)
// ---------------------------------------------------------------------------
__device__ float g_h  [Mrows * Dc];
__device__ float g_q  [Bc * Hc * Lc * DHc];   // [B,H,L,8]
__device__ float g_kb [Bc * Hc * Lc * DHc];
__device__ float g_vb [Bc * Hc * Lc * DHc];
__device__ float g_ctx[Mrows * Dc];
__device__ float g_ao [Mrows * Dc];
__device__ float g_f  [Mrows * DFFc];
__device__ float g_g2 [Mrows * Dc];
__device__ float g_pe [Lc * Dc];

// ---------------------------------------------------------------------------
// f32x2 packed-FMA helpers (PTX-only; doubles fp32 FMA throughput on sm_103a)
// ---------------------------------------------------------------------------
__device__ __forceinline__ ull pack2(float x, float y) {
    ull r; asm("mov.b64 %0, {%1, %2};" : "=l"(r) : "f"(x), "f"(y)); return r;
}
__device__ __forceinline__ void unpack2(ull v, float& x, float& y) {
    asm("mov.b64 {%0, %1}, %2;" : "=f"(x), "=f"(y) : "l"(v));
}
__device__ __forceinline__ void fma2(ull& d, ull a, ull b) {
    asm("fma.rn.f32x2 %0, %1, %2, %0;" : "+l"(d) : "l"(a), "l"(b));
}

// ---------------------------------------------------------------------------
// Positional encoding: pair j=d>>1, even->sin, odd->cos, 10000^(j/128)
// ---------------------------------------------------------------------------
__global__ void pe_kernel(float* __restrict__ pe) {
    int l = blockIdx.x;
    int d = threadIdx.x;
    int j = d >> 1;
    float pj  = powf(10000.0f, (float)j / 128.0f);
    float ang = (float)l / pj;
    pe[l * Dc + d] = (d & 1) ? cosf(ang) : sinf(ang);
}

// ---------------------------------------------------------------------------
// Tiled SGEMM: C[M,N] = A[M,K] @ W[N,K]^T (+bias, +epilogue)
// BM=64, BN=64, K fully resident (compile-time), 256 threads, 4x4 micro-tile.
// Smem tiles transposed ([k][m] / [k][n]); fill conflict-free (m/n across
// lanes). Inner loop: 1 LDS.128 (A) + 1 LDS.128-as-ulonglong2 (W pairs, no
// packing) + 4 A-dups + 8 FFMA2 per k-step -> FFMA2-pipe-bound.
// One __syncthreads total. Grid: (ceil(N/64), M/64) = 256..768 blocks.
// MODE: 0 bias | 1 bias+relu | 2 relu->BN->+pe | 3 qkv scatter [B,H,L,8]
// ---------------------------------------------------------------------------
template <int MODE, int K>
__global__ void __launch_bounds__(256)
gemm_k(const float* __restrict__ A, const float* __restrict__ W,
       const float* __restrict__ bias, float* __restrict__ C,
       int N,
       const float* __restrict__ e0, const float* __restrict__ e1,
       const float* __restrict__ e2, const float* __restrict__ e3,
       const float* __restrict__ e4,
       float* __restrict__ o1, float* __restrict__ o2)
{
    extern __shared__ float smem[];
    float* As = smem;             // [K][64]
    float* Ws = smem + K * 64;    // [K][64]

    const int tid  = threadIdx.x;
    const int tx   = tid & 15;    // col group: 4 cols
    const int ty   = tid >> 4;    // row group: 4 rows
    const int row0 = blockIdx.y * 64;
    const int col0 = blockIdx.x * 64;

    // ---- fill: row/col = tid&63, k-chunk = (tid>>6)*(K/4)
    {
        constexpr int KPT = K / 4;            // 32 or 20
        const int mf = tid & 63;
        const int kq = tid >> 6;              // 0..3
        const bool wvalid = (col0 + mf) < N;
        const float* Ap = A + (size_t)(row0 + mf) * K + kq * KPT;
        const float* Wp = W + (size_t)(col0 + mf) * K + kq * KPT;
        #pragma unroll
        for (int u = 0; u < KPT / 4; u++) {
            const int kk = kq * KPT + u * 4;
            float4 a4 = *(const float4*)(Ap + u * 4);
            As[(kk + 0) * 64 + mf] = a4.x;
            As[(kk + 1) * 64 + mf] = a4.y;
            As[(kk + 2) * 64 + mf] = a4.z;
            As[(kk + 3) * 64 + mf] = a4.w;
            float4 w4 = wvalid ? *(const float4*)(Wp + u * 4)
                               : make_float4(0.f, 0.f, 0.f, 0.f);
            Ws[(kk + 0) * 64 + mf] = w4.x;
            Ws[(kk + 1) * 64 + mf] = w4.y;
            Ws[(kk + 2) * 64 + mf] = w4.z;
            Ws[(kk + 3) * 64 + mf] = w4.w;
        }
    }
    __syncthreads();

    ull acc[4][2];
    #pragma unroll
    for (int i = 0; i < 4; i++) { acc[i][0] = 0ull; acc[i][1] = 0ull; }

    #pragma unroll 8
    for (int kk = 0; kk < K; kk++) {
        float4 a4 = *(const float4*)&As[kk * 64 + ty * 4];
        ulonglong2 w2 = *(const ulonglong2*)&Ws[kk * 64 + tx * 4];
        const ull d0 = pack2(a4.x, a4.x);
        const ull d1 = pack2(a4.y, a4.y);
        const ull d2 = pack2(a4.z, a4.z);
        const ull d3 = pack2(a4.w, a4.w);
        fma2(acc[0][0], d0, w2.x); fma2(acc[0][1], d0, w2.y);
        fma2(acc[1][0], d1, w2.x); fma2(acc[1][1], d1, w2.y);
        fma2(acc[2][0], d2, w2.x); fma2(acc[2][1], d2, w2.y);
        fma2(acc[3][0], d3, w2.x); fma2(acc[3][1], d3, w2.y);
    }

    // ---- epilogue: cols [colb, colb+4) fully in or out (N % 4 == 0)
    const int colb = col0 + tx * 4;
    if (colb + 3 >= N) return;

    float4 b4 = *(const float4*)(bias + colb);

    float4 gg, be, rm, rv;
    if (MODE == 2) {
        gg = *(const float4*)(e0 + colb);
        be = *(const float4*)(e1 + colb);
        rm = *(const float4*)(e2 + colb);
        rv = *(const float4*)(e3 + colb);
        gg.x *= rsqrtf(rv.x + 1e-5f); gg.y *= rsqrtf(rv.y + 1e-5f);
        gg.z *= rsqrtf(rv.z + 1e-5f); gg.w *= rsqrtf(rv.w + 1e-5f);
    }

    #pragma unroll
    for (int i = 0; i < 4; i++) {
        const int m = row0 + ty * 4 + i;
        float v[4];
        unpack2(acc[i][0], v[0], v[1]);
        unpack2(acc[i][1], v[2], v[3]);
        v[0] += b4.x; v[1] += b4.y; v[2] += b4.z; v[3] += b4.w;

        if (MODE == 0 || MODE == 1) {
            if (MODE == 1) {
                v[0] = fmaxf(v[0], 0.f); v[1] = fmaxf(v[1], 0.f);
                v[2] = fmaxf(v[2], 0.f); v[3] = fmaxf(v[3], 0.f);
            }
            *(float4*)(C + (size_t)m * N + colb) = make_float4(v[0], v[1], v[2], v[3]);
        } else if (MODE == 2) {
            const int l = m & (Lc - 1);
            float4 p4 = *(const float4*)(e4 + (size_t)l * Dc + colb);
            v[0] = fmaxf(v[0], 0.f); v[1] = fmaxf(v[1], 0.f);
            v[2] = fmaxf(v[2], 0.f); v[3] = fmaxf(v[3], 0.f);
            v[0] = (v[0] - rm.x) * gg.x + be.x + p4.x;
            v[1] = (v[1] - rm.y) * gg.y + be.y + p4.y;
            v[2] = (v[2] - rm.z) * gg.z + be.z + p4.z;
            v[3] = (v[3] - rm.w) * gg.w + be.w + p4.w;
            *(float4*)(C + (size_t)m * Dc + colb) = make_float4(v[0], v[1], v[2], v[3]);
        } else {  // MODE 3: qkv scatter -> [B,H,L,8]
            const int which = col0 >> 7;          // 0:q 1:k 2:v
            const int hh  = (colb & 127) >> 3;
            const int dhb = colb & 7;             // 0 or 4
            const int b   = m >> 11;
            const int l   = m & (Lc - 1);
            float* dst = (which == 0) ? C : ((which == 1) ? o1 : o2);
            float* dp = dst + (((size_t)(b * Hc + hh)) * Lc + l) * DHc + dhb;
            *(float4*)dp = make_float4(v[0], v[1], v[2], v[3]);
        }
    }
}

// ---------------------------------------------------------------------------
// Local-window attention: 4 queries/thread, 64 threads/block (256 q/block).
// Grid 512 blocks -> ~3.5 blocks/SM resident (vs 1.7 at 128thr) for latency
// hiding; K/V staged once as d-pair float2, each row read once serves 4
// queries. Window: 1 <= |j-q| <= 64 (diagonal excluded), 0 <= j < L.
// Softmax without max-subtraction (scores small; exact ratio in fp32).
// ---------------------------------------------------------------------------
#define ATHR  64
#define AQPT  4
#define AQB   (ATHR * AQPT)       // 256 queries per block
#define AROWS (AQB + 2 * WINc)    // 384 staged rows

__global__ void __launch_bounds__(ATHR)
attn_kernel(const float* __restrict__ Q, const float* __restrict__ Kb,
            const float* __restrict__ Vb, float* __restrict__ ctx)
{
    __shared__ float2 Kp[4][AROWS];
    __shared__ float2 Vp[4][AROWS];

    const int tid = threadIdx.x;
    const int q0  = blockIdx.x * AQB;
    const int bh  = blockIdx.y;               // b*H + h

    const float* kp = Kb + (size_t)bh * Lc * DHc;
    const float* vp = Vb + (size_t)bh * Lc * DHc;

    #pragma unroll
    for (int rr = 0; rr < AROWS / ATHR; rr++) {
        const int r = tid + rr * ATHR;
        const int g = q0 - WINc + r;
        if (g >= 0 && g < Lc) {
            float4 k0 = *(const float4*)(kp + (size_t)g * DHc);
            float4 k1 = *(const float4*)(kp + (size_t)g * DHc + 4);
            Kp[0][r] = make_float2(k0.x, k0.y);
            Kp[1][r] = make_float2(k0.z, k0.w);
            Kp[2][r] = make_float2(k1.x, k1.y);
            Kp[3][r] = make_float2(k1.z, k1.w);
            float4 v0 = *(const float4*)(vp + (size_t)g * DHc);
            float4 v1 = *(const float4*)(vp + (size_t)g * DHc + 4);
            Vp[0][r] = make_float2(v0.x, v0.y);
            Vp[1][r] = make_float2(v0.z, v0.w);
            Vp[2][r] = make_float2(v1.x, v1.y);
            Vp[3][r] = make_float2(v1.z, v1.w);
        } else {
            Kp[0][r] = Kp[1][r] = Kp[2][r] = Kp[3][r] = make_float2(0.f, 0.f);
            Vp[0][r] = Vp[1][r] = Vp[2][r] = Vp[3][r] = make_float2(0.f, 0.f);
        }
    }
    __syncthreads();

    const int qb = q0 + tid * AQPT;           // first of this thread's 4 queries

    ull qd[AQPT][4];
    #pragma unroll
    for (int i = 0; i < AQPT; i++) {
        const float* qp = Q + ((size_t)bh * Lc + qb + i) * DHc;
        float4 qa = *(const float4*)qp;
        float4 qv = *(const float4*)(qp + 4);
        qd[i][0] = pack2(qa.x, qa.y); qd[i][1] = pack2(qa.z, qa.w);
        qd[i][2] = pack2(qv.x, qv.y); qd[i][3] = pack2(qv.z, qv.w);
    }

    const float scale = 0.35355339059327373f; // 1/sqrt(8)
    float sum[AQPT] = {0.f, 0.f, 0.f, 0.f};
    ull c2[AQPT][4];
    #pragma unroll
    for (int i = 0; i < AQPT; i++)
        #pragma unroll
        for (int d = 0; d < 4; d++) c2[i][d] = 0ull;

    // jj scans keys j = qb - 64 + jj, jj in [0, 128 + AQPT)
    #pragma unroll 4
    for (int jj = 0; jj < 128 + AQPT; jj++) {
        const int r = tid * AQPT + jj;        // local staged row
        const int j = qb - WINc + jj;         // global key index
        const bool jok = ((unsigned)j < (unsigned)Lc);

        const ull k0 = *(const ull*)&Kp[0][r];
        const ull k1 = *(const ull*)&Kp[1][r];
        const ull k2 = *(const ull*)&Kp[2][r];
        const ull k3 = *(const ull*)&Kp[3][r];
        const ull v0 = *(const ull*)&Vp[0][r];
        const ull v1 = *(const ull*)&Vp[1][r];
        const ull v2 = *(const ull*)&Vp[2][r];
        const ull v3 = *(const ull*)&Vp[3][r];

        #pragma unroll
        for (int i = 0; i < AQPT; i++) {
            // offset of key from query i: doff = jj - 64 - i
            const int doff = jj - WINc - i;
            const bool ok = jok && (doff != 0) && (doff >= -WINc) && (doff <= WINc);
            ull s2 = 0ull;
            fma2(s2, qd[i][0], k0);
            fma2(s2, qd[i][1], k1);
            fma2(s2, qd[i][2], k2);
            fma2(s2, qd[i][3], k3);
            float slo, shi; unpack2(s2, slo, shi);
            float p = __expf((slo + shi) * scale);
            p = ok ? p : 0.0f;
            sum[i] += p;
            const ull p2 = pack2(p, p);
            fma2(c2[i][0], p2, v0);
            fma2(c2[i][1], p2, v1);
            fma2(c2[i][2], p2, v2);
            fma2(c2[i][3], p2, v3);
        }
    }

    const int hh = bh & (Hc - 1);
    const int b  = bh >> 4;
    #pragma unroll
    for (int i = 0; i < AQPT; i++) {
        const float inv = 1.0f / sum[i];
        float o[8];
        unpack2(c2[i][0], o[0], o[1]);
        unpack2(c2[i][1], o[2], o[3]);
        unpack2(c2[i][2], o[4], o[5]);
        unpack2(c2[i][3], o[6], o[7]);
        #pragma unroll
        for (int d = 0; d < 8; d++) o[d] *= inv;
        float* op = ctx + ((size_t)(b * Lc + qb + i)) * Dc + hh * DHc;
        *(float4*)op       = make_float4(o[0], o[1], o[2], o[3]);
        *(float4*)(op + 4) = make_float4(o[4], o[5], o[6], o[7]);
    }
}

// ---------------------------------------------------------------------------
// Launch
// ---------------------------------------------------------------------------
extern "C" void kernel_launch(void* const* d_in, const int* in_sizes, int n_in,
                              void* d_out, int out_size)
{
    const float* x         = (const float*)d_in[0];
    const float* conv_w    = (const float*)d_in[1];
    const float* conv_b    = (const float*)d_in[2];
    const float* bn_g      = (const float*)d_in[3];
    const float* bn_b      = (const float*)d_in[4];
    const float* bn_rm     = (const float*)d_in[5];
    const float* bn_rv     = (const float*)d_in[6];
    const float* in_proj_w = (const float*)d_in[7];
    const float* in_proj_b = (const float*)d_in[8];
    const float* out_w     = (const float*)d_in[9];
    const float* out_b     = (const float*)d_in[10];
    const float* ff_w1     = (const float*)d_in[11];
    const float* ff_b1     = (const float*)d_in[12];
    const float* ff_w2     = (const float*)d_in[13];
    const float* ff_b2     = (const float*)d_in[14];
    const float* fc_w      = (const float*)d_in[15];
    const float* fc_b      = (const float*)d_in[16];
    float* out = (float*)d_out;

    float *h, *q, *kb, *vb, *ctx, *ao, *f, *g2, *pe;
    cudaGetSymbolAddress((void**)&h,   g_h);
    cudaGetSymbolAddress((void**)&q,   g_q);
    cudaGetSymbolAddress((void**)&kb,  g_kb);
    cudaGetSymbolAddress((void**)&vb,  g_vb);
    cudaGetSymbolAddress((void**)&ctx, g_ctx);
    cudaGetSymbolAddress((void**)&ao,  g_ao);
    cudaGetSymbolAddress((void**)&f,   g_f);
    cudaGetSymbolAddress((void**)&g2,  g_g2);
    cudaGetSymbolAddress((void**)&pe,  g_pe);

    // dynamic smem sizes (two [K][64] tiles)
    const int SM80  = 2 * 80  * 64 * 4;   // 40960
    const int SM128 = 2 * 128 * 64 * 4;   // 65536

    cudaFuncSetAttribute(gemm_k<2, 80>,  cudaFuncAttributeMaxDynamicSharedMemorySize, SM80);
    cudaFuncSetAttribute(gemm_k<3, 128>, cudaFuncAttributeMaxDynamicSharedMemorySize, SM128);
    cudaFuncSetAttribute(gemm_k<0, 128>, cudaFuncAttributeMaxDynamicSharedMemorySize, SM128);
    cudaFuncSetAttribute(gemm_k<1, 128>, cudaFuncAttributeMaxDynamicSharedMemorySize, SM128);

    // 0) positional encoding
    pe_kernel<<<Lc, Dc>>>(pe);

    // 1) conv(k=1)+relu+BN+pe : K=80, N=128, grid (2,128)
    gemm_k<2, 80><<<dim3(2, Mrows / 64), 256, SM80>>>(x, conv_w, conv_b, h,
        Dc, bn_g, bn_b, bn_rm, bn_rv, pe, nullptr, nullptr);

    // 2) qkv projection -> scatter [B,H,L,8] : N=384, grid (6,128)
    gemm_k<3, 128><<<dim3(6, Mrows / 64), 256, SM128>>>(h, in_proj_w, in_proj_b, q,
        3 * Dc, nullptr, nullptr, nullptr, nullptr, nullptr, kb, vb);

    // 3) local-window attention -> ctx [B,L,128] : grid (8,64) = 512 blocks
    attn_kernel<<<dim3(Lc / AQB, Bc * Hc), ATHR>>>(q, kb, vb, ctx);

    // 4) out projection : grid (2,128)
    gemm_k<0, 128><<<dim3(2, Mrows / 64), 256, SM128>>>(ctx, out_w, out_b, ao,
        Dc, nullptr, nullptr, nullptr, nullptr, nullptr, nullptr, nullptr);

    // 5) ffn layer 1 (relu)
    gemm_k<1, 128><<<dim3(2, Mrows / 64), 256, SM128>>>(ao, ff_w1, ff_b1, f,
        DFFc, nullptr, nullptr, nullptr, nullptr, nullptr, nullptr, nullptr);

    // 6) ffn layer 2
    gemm_k<0, 128><<<dim3(2, Mrows / 64), 256, SM128>>>(f, ff_w2, ff_b2, g2,
        Dc, nullptr, nullptr, nullptr, nullptr, nullptr, nullptr, nullptr);

    // 7) final head -> [8192,80] : grid (2,128)
    gemm_k<0, 128><<<dim3(2, Mrows / 64), 256, SM128>>>(g2, fc_w, fc_b, out,
        DINc, nullptr, nullptr, nullptr, nullptr, nullptr, nullptr, nullptr);
}